// round 3
// baseline (speedup 1.0000x reference)
#include <cuda_runtime.h>
#include <cstdint>

#define MAXN 40000
#define MAXE 640000
#define HF 128
#define NH 8
#define NF 16

// ---------------- scratch (device globals: no runtime allocation) ----------------
__device__ float    g_xp[MAXN * HF];     // transformed features [N,128]
__device__ float    g_as[MAXN * NH];     // per-node src attention logits [N,8]
__device__ float    g_ad[MAXN * NH];     // per-node dst attention logits [N,8]
__device__ float    g_h [MAXN * HF];     // pre-BN output [N,128]
__device__ int      g_deg[MAXN];
__device__ int      g_cnt[MAXN];
__device__ int      g_off[MAXN + 1];
__device__ int      g_srcs[MAXE];        // CSR (by dst) source indices
__device__ float    g_cs[HF];            // column sums
__device__ float    g_cq[HF];            // column sums of squares
__device__ unsigned g_amax[NH * 32];     // per-head global max of a_s (encoded), stride 32

// ---------------- f32x2 packed helpers ----------------
__device__ __forceinline__ unsigned long long pk2(float a, float b) {
    unsigned long long r;
    asm("mov.b64 %0, {%1,%2};" : "=l"(r) : "f"(a), "f"(b));
    return r;
}
__device__ __forceinline__ void upk2(unsigned long long v, float& a, float& b) {
    asm("mov.b64 {%0,%1}, %2;" : "=f"(a), "=f"(b) : "l"(v));
}
__device__ __forceinline__ unsigned long long fma2(unsigned long long a,
                                                   unsigned long long b,
                                                   unsigned long long c) {
    unsigned long long d;
    asm("fma.rn.f32x2 %0, %1, %2, %3;" : "=l"(d) : "l"(a), "l"(b), "l"(c));
    return d;
}

// monotone float<->uint encoding for atomicMax on floats
__device__ __forceinline__ unsigned encf(float v) {
    unsigned b = __float_as_uint(v);
    return (b & 0x80000000u) ? ~b : (b | 0x80000000u);
}
__device__ __forceinline__ float decf(unsigned k) {
    unsigned b = (k & 0x80000000u) ? (k & 0x7FFFFFFFu) : ~k;
    return __uint_as_float(b);
}

// ---------------- K1: GEMM xp = x @ W  + attention projections + per-head max ----------------
// 64-row x 128-col tile per block, 256 threads, thread computes 8x4 micro-tile.
__global__ __launch_bounds__(256) void gemm_kernel(const float* __restrict__ X,
                                                   const float* __restrict__ W,
                                                   const float* __restrict__ attS,
                                                   const float* __restrict__ attD,
                                                   int n) {
    __shared__ float xs[64][36];
    __shared__ float ws[32][128];
    __shared__ unsigned s_amax[NH];

    int t  = threadIdx.x;
    int tx = t & 31;                 // lane; cols 4*tx..4*tx+3
    int ty = t >> 5;                 // warp; rows ty*8..ty*8+7
    int row0 = blockIdx.x * 64;

    if (t < NH) s_amax[t] = 0u;

    unsigned long long acc[8][2];
#pragma unroll
    for (int i = 0; i < 8; i++) { acc[i][0] = 0ull; acc[i][1] = 0ull; }

    for (int kk = 0; kk < 128; kk += 32) {
#pragma unroll
        for (int rep = 0; rep < 2; rep++) {
            int id = t + rep * 256;
            int r  = id >> 3;
            int c4 = id & 7;
            int row = row0 + r; if (row >= n) row = n - 1;
            float4 v = *(const float4*)(X + (long long)row * 128 + kk + c4 * 4);
            *(float4*)&xs[r][c4 * 4] = v;
        }
#pragma unroll
        for (int rep = 0; rep < 4; rep++) {
            int id = t + rep * 256;
            int r  = id >> 5;
            int c4 = id & 31;
            float4 v = *(const float4*)(W + (kk + r) * 128 + c4 * 4);
            *(float4*)&ws[r][c4 * 4] = v;
        }
        __syncthreads();
#pragma unroll
        for (int k = 0; k < 32; k++) {
            float4 w = *(const float4*)&ws[k][tx * 4];
            unsigned long long w01 = pk2(w.x, w.y);
            unsigned long long w23 = pk2(w.z, w.w);
#pragma unroll
            for (int i = 0; i < 8; i++) {
                float xv = xs[ty * 8 + i][k];
                unsigned long long xd = pk2(xv, xv);
                acc[i][0] = fma2(w01, xd, acc[i][0]);
                acc[i][1] = fma2(w23, xd, acc[i][1]);
            }
        }
        __syncthreads();
    }

    // epilogue: store xp, compute a_s/a_d via quad reduce, track per-head max(a_s)
    int h = tx >> 2;
    float4 As4 = *(const float4*)(attS + h * NF + (tx & 3) * 4);
    float4 Ad4 = *(const float4*)(attD + h * NF + (tx & 3) * 4);
    float amax = -3.0e38f;
#pragma unroll
    for (int i = 0; i < 8; i++) {
        float4 o;
        upk2(acc[i][0], o.x, o.y);
        upk2(acc[i][1], o.z, o.w);
        int row = row0 + ty * 8 + i;
        if (row < n) *(float4*)(g_xp + (long long)row * 128 + tx * 4) = o;
        float s = o.x * As4.x + o.y * As4.y + o.z * As4.z + o.w * As4.w;
        float d = o.x * Ad4.x + o.y * Ad4.y + o.z * Ad4.z + o.w * Ad4.w;
        s += __shfl_xor_sync(0xffffffffu, s, 1);
        s += __shfl_xor_sync(0xffffffffu, s, 2);
        d += __shfl_xor_sync(0xffffffffu, d, 1);
        d += __shfl_xor_sync(0xffffffffu, d, 2);
        if ((tx & 3) == 0 && row < n) {
            g_as[row * NH + h] = s;
            g_ad[row * NH + h] = d;
        }
        amax = fmaxf(amax, s);   // clamped rows hold a real row's value -> safe upper bound
    }
    if ((tx & 3) == 0) atomicMax(&s_amax[h], encf(amax));
    __syncthreads();
    if (t < NH) atomicMax(&g_amax[t * 32], s_amax[t]);
}

// ---------------- K2: degree histogram over dst (int4) ----------------
__global__ void hist_kernel(const int* __restrict__ dsts, int e) {
    int base = (blockIdx.x * blockDim.x + threadIdx.x) * 4;
    if (base >= e) return;
    if (base + 4 <= e) {
        int4 d = *(const int4*)(dsts + base);
        atomicAdd(&g_deg[d.x], 1);
        atomicAdd(&g_deg[d.y], 1);
        atomicAdd(&g_deg[d.z], 1);
        atomicAdd(&g_deg[d.w], 1);
    } else {
        for (int k = base; k < e; k++) atomicAdd(&g_deg[dsts[k]], 1);
    }
}

// ---------------- K3: exclusive scan -> offsets; clears deg/cnt/cs/cq ----------------
__global__ __launch_bounds__(1024) void scan_kernel(int n) {
    const int T = 1024;
    int t = threadIdx.x;
    int chunk = (n + T - 1) / T;
    int start = t * chunk;
    int end   = min(start + chunk, n);
    int sum = 0;
    for (int i = start; i < end; i++) sum += g_deg[i];

    __shared__ int wsum[32];
    int lane = t & 31, wid = t >> 5;
    int v = sum;
#pragma unroll
    for (int o = 1; o < 32; o <<= 1) {
        int u = __shfl_up_sync(0xffffffffu, v, o);
        if (lane >= o) v += u;
    }
    if (lane == 31) wsum[wid] = v;
    __syncthreads();
    if (wid == 0) {
        int w = wsum[lane];
#pragma unroll
        for (int o = 1; o < 32; o <<= 1) {
            int u = __shfl_up_sync(0xffffffffu, w, o);
            if (lane >= o) w += u;
        }
        wsum[lane] = w;
    }
    __syncthreads();
    int excl = v - sum + (wid > 0 ? wsum[wid - 1] : 0);
    int run = excl;
    for (int i = start; i < end; i++) {
        g_off[i] = run;
        run += g_deg[i];
        g_deg[i] = 0;          // reset for next replay
        g_cnt[i] = 0;          // reset before scatter
    }
    if (start < n && end == n) g_off[n] = run;
    if (t < HF) { g_cs[t] = 0.f; g_cq[t] = 0.f; }   // reset before aggregate
}

// ---------------- K4: scatter edges into CSR-by-dst (int4) ----------------
__global__ void scatter_kernel(const int* __restrict__ ei, int e) {
    int base = (blockIdx.x * blockDim.x + threadIdx.x) * 4;
    if (base >= e) return;
    const int* dsts = ei + e;
    if (base + 4 <= e) {
        int4 s4 = *(const int4*)(ei + base);
        int4 d4 = *(const int4*)(dsts + base);
        g_srcs[g_off[d4.x] + atomicAdd(&g_cnt[d4.x], 1)] = s4.x;
        g_srcs[g_off[d4.y] + atomicAdd(&g_cnt[d4.y], 1)] = s4.y;
        g_srcs[g_off[d4.z] + atomicAdd(&g_cnt[d4.z], 1)] = s4.z;
        g_srcs[g_off[d4.w] + atomicAdd(&g_cnt[d4.w], 1)] = s4.w;
    } else {
        for (int k = base; k < e; k++)
            g_srcs[g_off[dsts[k]] + atomicAdd(&g_cnt[dsts[k]], 1)] = ei[k];
    }
}

// ---------------- K5: per-node softmax-aggregate (one warp per node, single edge pass)
//                      + fused BN column statistics ----------------
__global__ __launch_bounds__(256) void aggregate_kernel(const float* __restrict__ bias,
                                                        int n, int nwarps) {
    __shared__ float s_cs[HF];
    __shared__ float s_cq[HF];
    int t = threadIdx.x;
    if (t < HF) { s_cs[t] = 0.f; s_cq[t] = 0.f; }
    __syncthreads();

    int lane = t & 31;
    int gw   = (blockIdx.x * blockDim.x + t) >> 5;
    int hB   = lane & 7;
    int jB   = lane >> 3;
    int srcl = lane >> 2;

    const float4 b4 = *(const float4*)(bias + lane * 4);
    const float  Ah = decf(g_amax[hB * 32]);   // per-head global max of a_s

    float4 accS = make_float4(0.f, 0.f, 0.f, 0.f);
    float4 accQ = make_float4(0.f, 0.f, 0.f, 0.f);

    for (int node = gw; node < n; node += nwarps) {
        int beg = g_off[node];
        int deg = g_off[node + 1] - beg;

        float ad_h = g_ad[node * NH + hB];
        float as_h = g_as[node * NH + hB];
        float mAh  = Ah + ad_h;
        float m    = fmaxf(mAh, 0.2f * mAh);          // lrelu(Ah + a_d) >= all edge logits
        float vs   = as_h + ad_h;
        float es   = fmaxf(vs, 0.2f * vs);
        float pself = __expf(es - m);
        float ssum  = (jB == 0) ? pself : 0.f;

        float4 acc = make_float4(0.f, 0.f, 0.f, 0.f);
        for (int c = 0; c < deg; c += 4) {
            int  eoff  = c + jB;
            bool valid = eoff < deg;
            int  s = valid ? g_srcs[beg + eoff] : 0;
            float asx = g_as[s * NH + hB];
            float vv = asx + ad_h;
            float el = fmaxf(vv, 0.2f * vv);
            float p = valid ? __expf(el - m) : 0.f;
            ssum += p;

            int s0 = __shfl_sync(0xffffffffu, s, 0);
            int s1 = __shfl_sync(0xffffffffu, s, 8);
            int s2 = __shfl_sync(0xffffffffu, s, 16);
            int s3 = __shfl_sync(0xffffffffu, s, 24);
            float4 x0 = *(const float4*)(g_xp + (long long)s0 * 128 + lane * 4);
            float4 x1 = *(const float4*)(g_xp + (long long)s1 * 128 + lane * 4);
            float4 x2 = *(const float4*)(g_xp + (long long)s2 * 128 + lane * 4);
            float4 x3 = *(const float4*)(g_xp + (long long)s3 * 128 + lane * 4);
            float p0 = __shfl_sync(0xffffffffu, p, 0 + srcl);
            float p1 = __shfl_sync(0xffffffffu, p, 8 + srcl);
            float p2 = __shfl_sync(0xffffffffu, p, 16 + srcl);
            float p3 = __shfl_sync(0xffffffffu, p, 24 + srcl);
            acc.x += p0 * x0.x + p1 * x1.x + p2 * x2.x + p3 * x3.x;
            acc.y += p0 * x0.y + p1 * x1.y + p2 * x2.y + p3 * x3.y;
            acc.z += p0 * x0.z + p1 * x1.z + p2 * x2.z + p3 * x3.z;
            acc.w += p0 * x0.w + p1 * x1.w + p2 * x2.w + p3 * x3.w;
        }
        ssum += __shfl_xor_sync(0xffffffffu, ssum, 8);
        ssum += __shfl_xor_sync(0xffffffffu, ssum, 16);
        float sacc = __shfl_sync(0xffffffffu, ssum,  srcl);
        float psf  = __shfl_sync(0xffffffffu, pself, srcl);
        float inv  = 1.0f / (sacc + 1e-16f);

        float4 xn = *(const float4*)(g_xp + (long long)node * 128 + lane * 4);
        float4 hv;
        hv.x = (acc.x + psf * xn.x) * inv + b4.x;
        hv.y = (acc.y + psf * xn.y) * inv + b4.y;
        hv.z = (acc.z + psf * xn.z) * inv + b4.z;
        hv.w = (acc.w + psf * xn.w) * inv + b4.w;
        *(float4*)(g_h + (long long)node * 128 + lane * 4) = hv;

        accS.x += hv.x; accS.y += hv.y; accS.z += hv.z; accS.w += hv.w;
        accQ.x += hv.x * hv.x; accQ.y += hv.y * hv.y;
        accQ.z += hv.z * hv.z; accQ.w += hv.w * hv.w;
    }

    // merge warp-local column stats into block smem, then to global
    int c0 = lane * 4;
    atomicAdd(&s_cs[c0 + 0], accS.x); atomicAdd(&s_cs[c0 + 1], accS.y);
    atomicAdd(&s_cs[c0 + 2], accS.z); atomicAdd(&s_cs[c0 + 3], accS.w);
    atomicAdd(&s_cq[c0 + 0], accQ.x); atomicAdd(&s_cq[c0 + 1], accQ.y);
    atomicAdd(&s_cq[c0 + 2], accQ.z); atomicAdd(&s_cq[c0 + 3], accQ.w);
    __syncthreads();
    if (t < HF) {
        atomicAdd(&g_cs[t], s_cs[t]);
        atomicAdd(&g_cq[t], s_cq[t]);
    }
}

// ---------------- K6: BN + ReLU + residual (float4) ----------------
__global__ __launch_bounds__(256) void finalize_kernel(const float* __restrict__ x,
                                                       const float* __restrict__ gamma,
                                                       const float* __restrict__ beta,
                                                       float* __restrict__ out, int n) {
    __shared__ float sc[HF], sh[HF];
    int t = threadIdx.x;
    if (t < HF) {
        float invn = 1.0f / (float)n;
        float mean = g_cs[t] * invn;
        float var  = g_cq[t] * invn - mean * mean;
        float scl  = rsqrtf(var + 1e-5f) * gamma[t];
        sc[t] = scl;
        sh[t] = beta[t] - mean * scl;
    }
    __syncthreads();
    long long idx = (long long)blockIdx.x * blockDim.x + t;   // float4 index
    long long tot = (long long)n * 32;
    if (idx < tot) {
        int c = (int)(idx & 31) * 4;
        float4 h  = ((const float4*)g_h)[idx];
        float4 xv = ((const float4*)x)[idx];
        float4 y;
        y.x = fmaxf(h.x * sc[c + 0] + sh[c + 0], 0.f) + xv.x;
        y.y = fmaxf(h.y * sc[c + 1] + sh[c + 1], 0.f) + xv.y;
        y.z = fmaxf(h.z * sc[c + 2] + sh[c + 2], 0.f) + xv.z;
        y.w = fmaxf(h.w * sc[c + 3] + sh[c + 3], 0.f) + xv.w;
        ((float4*)out)[idx] = y;
    }
    if (blockIdx.x == 0 && t < NH) g_amax[t * 32] = 0u;   // reset for next replay
}

// ---------------- launch ----------------
extern "C" void kernel_launch(void* const* d_in, const int* in_sizes, int n_in,
                              void* d_out, int out_size) {
    const float* x       = (const float*)d_in[0];
    const int*   ei      = (const int*)d_in[1];
    const float* W       = (const float*)d_in[2];
    const float* att_src = (const float*)d_in[3];
    const float* att_dst = (const float*)d_in[4];
    const float* bias    = (const float*)d_in[5];
    const float* gamma   = (const float*)d_in[6];
    const float* beta    = (const float*)d_in[7];
    float* out = (float*)d_out;

    int n = in_sizes[0] / HF;       // 40000
    int e = in_sizes[1] / 2;        // 640000

    int e4blocks = (e / 4 + 256) / 256;   // covers tail
    gemm_kernel<<<(n + 63) / 64, 256>>>(x, W, att_src, att_dst, n);
    hist_kernel<<<e4blocks, 256>>>(ei + e, e);
    scan_kernel<<<1, 1024>>>(n);
    scatter_kernel<<<e4blocks, 256>>>(ei, e);
    const int AGG_BLOCKS = 740;
    aggregate_kernel<<<AGG_BLOCKS, 256>>>(bias, n, AGG_BLOCKS * 8);
    finalize_kernel<<<(int)(((long long)n * 32 + 255) / 256), 256>>>(x, gamma, beta, out, n);
}